// round 1
// baseline (speedup 1.0000x reference)
#include <cuda_runtime.h>
#include <cuda_bf16.h>
#include <math.h>

#define NN 100000
#define EE 200000
#define GG 4096
#define DD 300
#define HH 600
#define LL 5
#define DECH 1200
#define MAXO 1783

// ---------------- scratch (device globals; no allocation allowed) ----------------
__device__ float    g_h [(size_t)NN*DD];
__device__ float    g_z [(size_t)NN*DD];
__device__ float    g_y [(size_t)NN*HH];
__device__ float    g_stats[2*DECH];
__device__ float    g_scale[DECH];
__device__ float    g_shift[DECH];
__device__ unsigned g_hg[(size_t)GG*DD];
__device__ float    g_s [(size_t)GG*DD];
__device__ float    g_d [(size_t)GG*HH];
__device__ float    g_mu[(size_t)GG*DD];
__device__ float    g_dz[(size_t)GG*DECH];

// ---------------- elementwise kernels ----------------
__global__ void k_zero(float* p, int n) {
    int i = blockIdx.x * blockDim.x + threadIdx.x;
    if (i < n) p[i] = 0.f;
}

__global__ void k_zero_u(unsigned* p, int n) {
    int i = blockIdx.x * blockDim.x + threadIdx.x;
    if (i < n) p[i] = 0u;
}

__global__ void k_init_h(const float* __restrict__ atom_emb, const int* __restrict__ x_idx,
                         float* __restrict__ h) {
    long i = (long)blockIdx.x * blockDim.x + threadIdx.x;
    long total = (long)NN * DD;
    if (i >= total) return;
    int n = (int)(i / DD);
    int d = (int)(i - (long)n * DD);
    h[i] = atom_emb[(size_t)x_idx[n] * DD + d];
}

__global__ void k_init_z(const float* __restrict__ h, const float* __restrict__ epsp,
                         float* __restrict__ z) {
    long i = (long)blockIdx.x * blockDim.x + threadIdx.x;
    long total = (long)NN * DD;
    if (i >= total) return;
    z[i] = (1.f + *epsp) * h[i];
}

// msg = relu(h[src] + edge_emb[attr]); atomicAdd into z[dst]
__global__ void k_edge(const float* __restrict__ h, const float* __restrict__ ee,
                       const int* __restrict__ attr, const int* __restrict__ ei,
                       float* __restrict__ z) {
    long i = (long)blockIdx.x * blockDim.x + threadIdx.x;
    long total = (long)EE * DD;
    if (i >= total) return;
    int e = (int)(i / DD);
    int d = (int)(i - (long)e * DD);
    int src = ei[e];
    int dst = ei[EE + e];
    float m = h[(size_t)src * DD + d] + ee[(size_t)attr[e] * DD + d];
    if (m > 0.f) atomicAdd(&z[(size_t)dst * DD + d], m);
}

// ---------------- batchnorm ----------------
__global__ void k_bn_stats(const float* __restrict__ X, int M, int C, float* __restrict__ sums) {
    int r0 = blockIdx.x * 128;
    int rend = r0 + 128; if (rend > M) rend = M;
    for (int c = threadIdx.x; c < C; c += blockDim.x) {
        float s = 0.f, q = 0.f;
        for (int r = r0; r < rend; r++) {
            float v = X[(size_t)r * C + c];
            s += v; q += v * v;
        }
        atomicAdd(&sums[c], s);
        atomicAdd(&sums[C + c], q);
    }
}

__global__ void k_bn_final(const float* __restrict__ sums, float invM, int C,
                           const float* __restrict__ gamma, const float* __restrict__ beta,
                           float* __restrict__ scale, float* __restrict__ shift) {
    int c = blockIdx.x * blockDim.x + threadIdx.x;
    if (c >= C) return;
    float mean = sums[c] * invM;
    float var  = sums[C + c] * invM - mean * mean;
    float istd = rsqrtf(var + 1e-5f);
    float sc = istd * gamma[c];
    scale[c] = sc;
    shift[c] = beta[c] - mean * sc;
}

// mode 0: X = relu(bn)      (in place)
// mode 1: res += relu(bn)
// mode 2: res += bn
// mode 3: X = gelu_exact(bn) (in place)
__global__ void k_bn_apply(float* __restrict__ X, float* __restrict__ res,
                           const float* __restrict__ scale, const float* __restrict__ shift,
                           long total, int C, int mode) {
    long i = (long)blockIdx.x * blockDim.x + threadIdx.x;
    if (i >= total) return;
    int c = (int)(i % C);
    float v = X[i] * scale[c] + shift[c];
    if (mode == 0)      X[i] = fmaxf(v, 0.f);
    else if (mode == 1) res[i] += fmaxf(v, 0.f);
    else if (mode == 2) res[i] += v;
    else                X[i] = 0.5f * v * (1.f + erff(v * 0.70710678118654752f));
}

// ---------------- pooling / head elementwise ----------------
__device__ __forceinline__ unsigned enc_f(float x) {
    unsigned u = __float_as_uint(x);
    return (u & 0x80000000u) ? ~u : (u | 0x80000000u);
}

__global__ void k_segmax(const float* __restrict__ h, const int* __restrict__ batch,
                         unsigned* __restrict__ hg) {
    long i = (long)blockIdx.x * blockDim.x + threadIdx.x;
    long total = (long)NN * DD;
    if (i >= total) return;
    int n = (int)(i / DD);
    int d = (int)(i - (long)n * DD);
    atomicMax(&hg[(size_t)batch[n] * DD + d], enc_f(h[i]));
}

__global__ void k_decode_silu(const unsigned* __restrict__ hg, float* __restrict__ s, int total) {
    int i = blockIdx.x * blockDim.x + threadIdx.x;
    if (i >= total) return;
    unsigned u = hg[i];
    u = (u & 0x80000000u) ? (u & 0x7fffffffu) : ~u;
    float x = __uint_as_float(u);
    s[i] = x / (1.f + expf(-x));
}

// split d (G x 600) into mu -> out[0..], g_mu, and sigma=softplus+1e-7 -> out[offS..]
__global__ void k_split(const float* __restrict__ d, float* __restrict__ out,
                        float* __restrict__ mu, long offS) {
    long i = (long)blockIdx.x * blockDim.x + threadIdx.x;
    long total = (long)GG * HH;
    if (i >= total) return;
    int g = (int)(i / HH);
    int c = (int)(i - (long)g * HH);
    float v = d[i];
    if (c < DD) {
        out[(size_t)g * DD + c] = v;
        mu[(size_t)g * DD + c]  = v;
    } else {
        float sp = fmaxf(v, 0.f) + log1pf(expf(-fabsf(v))) + 1e-7f;
        out[offS + (size_t)g * DD + (c - DD)] = sp;
    }
}

// ---------------- GEMM: C[M x Nc] = A[M x K] @ B[K x Nc] + bias ----------------
// 64x64 tile, 256 threads, each 4x4 micro-tile, K-step 16. Row-major, strided.
__global__ void k_gemm(const float* __restrict__ A, int lda,
                       const float* __restrict__ B, int ldb,
                       const float* __restrict__ bias,
                       float* __restrict__ C, int ldc,
                       int M, int Nc, int K) {
    __shared__ float As[16][64];
    __shared__ float Bs[16][64];
    int tx = threadIdx.x;          // 0..15
    int ty = threadIdx.y;          // 0..15
    int tid = ty * 16 + tx;
    int row0 = blockIdx.y * 64;
    int col0 = blockIdx.x * 64;

    float acc[4][4] = {};

    for (int kt = 0; kt < K; kt += 16) {
#pragma unroll
        for (int i = 0; i < 4; i++) {
            int idx = tid + i * 256;
            int m = idx >> 4, k = idx & 15;
            int gm = row0 + m, gk = kt + k;
            As[k][m] = (gm < M && gk < K) ? A[(size_t)gm * lda + gk] : 0.f;
        }
#pragma unroll
        for (int i = 0; i < 4; i++) {
            int idx = tid + i * 256;
            int k = idx >> 6, n = idx & 63;
            int gk = kt + k, gn = col0 + n;
            Bs[k][n] = (gk < K && gn < Nc) ? B[(size_t)gk * ldb + gn] : 0.f;
        }
        __syncthreads();
#pragma unroll
        for (int k = 0; k < 16; k++) {
            float4 a4 = *reinterpret_cast<const float4*>(&As[k][ty * 4]);
            float4 b4 = *reinterpret_cast<const float4*>(&Bs[k][tx * 4]);
            float ar[4] = {a4.x, a4.y, a4.z, a4.w};
            float br[4] = {b4.x, b4.y, b4.z, b4.w};
#pragma unroll
            for (int i = 0; i < 4; i++)
#pragma unroll
                for (int j = 0; j < 4; j++)
                    acc[i][j] += ar[i] * br[j];
        }
        __syncthreads();
    }

#pragma unroll
    for (int i = 0; i < 4; i++) {
        int gm = row0 + ty * 4 + i;
        if (gm >= M) continue;
#pragma unroll
        for (int j = 0; j < 4; j++) {
            int gn = col0 + tx * 4 + j;
            if (gn >= Nc) continue;
            float b = bias ? bias[gn] : 0.f;
            C[(size_t)gm * ldc + gn] = acc[i][j] + b;
        }
    }
}

// ---------------- host side ----------------
static void gemm(const float* A, int lda, const float* B, int ldb, const float* bias,
                 float* C, int ldc, int M, int Nc, int K) {
    dim3 bl(16, 16);
    dim3 gr((Nc + 63) / 64, (M + 63) / 64);
    k_gemm<<<gr, bl>>>(A, lda, B, ldb, bias, C, ldc, M, Nc, K);
}

static void run_bn(float* stats, float* scale, float* shift,
                   const float* X, int M, int C, const float* gamma, const float* beta) {
    k_zero<<<(2 * C + 255) / 256, 256>>>(stats, 2 * C);
    k_bn_stats<<<(M + 127) / 128, 256>>>(X, M, C, stats);
    k_bn_final<<<(C + 255) / 256, 256>>>(stats, 1.f / (float)M, C, gamma, beta, scale, shift);
}

extern "C" void kernel_launch(void* const* d_in, const int* in_sizes, int n_in,
                              void* d_out, int out_size) {
    const float* atom_emb   = (const float*)d_in[0];
    const float* edge_emb   = (const float*)d_in[1];
    const float* eps        = (const float*)d_in[2];
    const float* conv_w1    = (const float*)d_in[3];
    const float* conv_b1    = (const float*)d_in[4];
    const float* conv_bn1_g = (const float*)d_in[5];
    const float* conv_bn1_b = (const float*)d_in[6];
    const float* conv_w2    = (const float*)d_in[7];
    const float* conv_b2    = (const float*)d_in[8];
    const float* bn_g       = (const float*)d_in[9];
    const float* bn_b       = (const float*)d_in[10];
    const float* dist_w     = (const float*)d_in[11];
    const float* dist_b     = (const float*)d_in[12];
    const float* dec_w1     = (const float*)d_in[13];
    const float* dec_b1     = (const float*)d_in[14];
    const float* dec_bn_g   = (const float*)d_in[15];
    const float* dec_bn_b   = (const float*)d_in[16];
    const float* dec_w2     = (const float*)d_in[17];
    const float* dec_b2     = (const float*)d_in[18];
    const int*   x_idx      = (const int*)d_in[19];
    const int*   edge_attr  = (const int*)d_in[20];
    const int*   edge_index = (const int*)d_in[21];
    const int*   batch      = (const int*)d_in[22];
    float* out = (float*)d_out;

    float *h, *z, *y, *stats, *scale, *shift, *s, *dbuf, *mu, *dz;
    unsigned* hg;
    cudaGetSymbolAddress((void**)&h,     g_h);
    cudaGetSymbolAddress((void**)&z,     g_z);
    cudaGetSymbolAddress((void**)&y,     g_y);
    cudaGetSymbolAddress((void**)&stats, g_stats);
    cudaGetSymbolAddress((void**)&scale, g_scale);
    cudaGetSymbolAddress((void**)&shift, g_shift);
    cudaGetSymbolAddress((void**)&hg,    g_hg);
    cudaGetSymbolAddress((void**)&s,     g_s);
    cudaGetSymbolAddress((void**)&dbuf,  g_d);
    cudaGetSymbolAddress((void**)&mu,    g_mu);
    cudaGetSymbolAddress((void**)&dz,    g_dz);

    const long ND = (long)NN * DD;
    const long NH = (long)NN * HH;
    const long ED = (long)EE * DD;

    // h = atom_emb[x_idx]
    k_init_h<<<(int)((ND + 255) / 256), 256>>>(atom_emb, x_idx, h);

    for (int l = 0; l < LL; l++) {
        // z = (1+eps)*h ; z += segment_sum(relu(h[src]+e), dst)
        k_init_z<<<(int)((ND + 255) / 256), 256>>>(h, eps + l, z);
        k_edge<<<(int)((ED + 255) / 256), 256>>>(h, edge_emb + (size_t)l * 5 * DD,
                                                 edge_attr, edge_index, z);
        // y = z @ w1 + b1 ; y = relu(bn1(y))
        gemm(z, DD, conv_w1 + (size_t)l * DD * HH, HH, conv_b1 + (size_t)l * HH,
             y, HH, NN, HH, DD);
        run_bn(stats, scale, shift, y, NN, HH,
               conv_bn1_g + (size_t)l * HH, conv_bn1_b + (size_t)l * HH);
        k_bn_apply<<<(int)((NH + 255) / 256), 256>>>(y, nullptr, scale, shift, NH, HH, 0);
        // z = y @ w2 + b2 ; h += (relu?)(bn2(z))
        gemm(y, HH, conv_w2 + (size_t)l * HH * DD, DD, conv_b2 + (size_t)l * DD,
             z, DD, NN, DD, HH);
        run_bn(stats, scale, shift, z, NN, DD,
               bn_g + (size_t)l * DD, bn_b + (size_t)l * DD);
        k_bn_apply<<<(int)((ND + 255) / 256), 256>>>(z, h, scale, shift, ND, DD,
                                                     (l < LL - 1) ? 1 : 2);
    }

    // segment_max pooling -> silu
    int GD = GG * DD;
    k_zero_u<<<(GD + 255) / 256, 256>>>(hg, GD);
    k_segmax<<<(int)((ND + 255) / 256), 256>>>(h, batch, hg);
    k_decode_silu<<<(GD + 255) / 256, 256>>>(hg, s, GD);

    // d = silu(h_graph) @ dist_w + dist_b
    gemm(s, DD, dist_w, HH, dist_b, dbuf, HH, GG, HH, DD);

    // mu / sigma split
    const long OFF_SG = (long)GG * DD;
    k_split<<<(int)(((long)GG * HH + 255) / 256), 256>>>(dbuf, out, mu, OFF_SG);

    // decoder heads
    const long OFF_O0   = 2L * GG * DD;
    const long OFF_GENE = OFF_O0 + (long)GG * 1024;
    const long OFF_CELL = OFF_GENE + (long)GG * 1973;
    const long OFF_O5   = OFF_CELL + (long)GG * 2749;

    const int  dims[6] = {1024, 1111, 862, 1783, 966, 978};
    const long base[6] = {OFF_O0, OFF_GENE, OFF_GENE + 1111, OFF_CELL, OFF_CELL + 1783, OFF_O5};
    const int  ldcs[6] = {1024, 1973, 1973, 2749, 2749, 978};

    const long GDH = (long)GG * DECH;
    for (int i = 0; i < 6; i++) {
        gemm(mu, DD, dec_w1 + (size_t)i * DD * DECH, DECH, dec_b1 + (size_t)i * DECH,
             dz, DECH, GG, DECH, DD);
        run_bn(stats, scale, shift, dz, GG, DECH,
               dec_bn_g + (size_t)i * DECH, dec_bn_b + (size_t)i * DECH);
        k_bn_apply<<<(int)((GDH + 255) / 256), 256>>>(dz, nullptr, scale, shift, GDH, DECH, 3);
        gemm(dz, DECH, dec_w2 + (size_t)i * DECH * MAXO, MAXO, dec_b2 + (size_t)i * MAXO,
             out + base[i], ldcs[i], GG, dims[i], DECH);
    }
}

// round 3
// speedup vs baseline: 2.8056x; 2.8056x over previous
#include <cuda_runtime.h>
#include <cuda_bf16.h>
#include <math.h>
#include <stdint.h>

#define NN 100000
#define EE 200000
#define GG 4096
#define DD 300
#define HH 600
#define LL 5
#define DECH 1200
#define MAXO 1783

// ---------------- scratch (device globals; no allocation allowed) ----------------
__device__ float    g_h [(size_t)NN*DD];
__device__ float    g_z [(size_t)NN*DD];
__device__ float    g_y [(size_t)NN*HH];
__device__ float    g_stats[2*DECH];
__device__ float    g_scale[DECH];
__device__ float    g_shift[DECH];
__device__ unsigned g_hg[(size_t)GG*DD];
__device__ float    g_s [(size_t)GG*DD];
__device__ float    g_d [(size_t)GG*HH];
__device__ float    g_mu[(size_t)GG*DD];
__device__ float    g_dz[(size_t)GG*DECH];
// transposed weights (fp32)
__device__ float    g_w1t[(size_t)LL*HH*DD];
__device__ float    g_w2t[(size_t)LL*DD*HH];
__device__ float    g_dwt[(size_t)HH*DD];
__device__ float    g_d1t[(size_t)6*DECH*DD];
__device__ float    g_d2t[(size_t)6*MAXO*DECH];

// ================= helpers =================
__device__ __forceinline__ uint32_t smem_u32(const void* p) {
    uint32_t a;
    asm("{ .reg .u64 t; cvta.to.shared.u64 t, %1; cvt.u32.u64 %0, t; }" : "=r"(a) : "l"(p));
    return a;
}
__device__ __forceinline__ uint32_t pk(__nv_bfloat16 a, __nv_bfloat16 b) {
    return (uint32_t)__bfloat16_as_ushort(a) | ((uint32_t)__bfloat16_as_ushort(b) << 16);
}
__device__ __forceinline__ void cvt4(float4 v, uint2& hi, uint2& lo) {
    __nv_bfloat16 hx = __float2bfloat16(v.x), hy = __float2bfloat16(v.y);
    __nv_bfloat16 hz = __float2bfloat16(v.z), hw = __float2bfloat16(v.w);
    __nv_bfloat16 lx = __float2bfloat16(v.x - __bfloat162float(hx));
    __nv_bfloat16 ly = __float2bfloat16(v.y - __bfloat162float(hy));
    __nv_bfloat16 lz = __float2bfloat16(v.z - __bfloat162float(hz));
    __nv_bfloat16 lw = __float2bfloat16(v.w - __bfloat162float(hw));
    hi = make_uint2(pk(hx, hy), pk(hz, hw));
    lo = make_uint2(pk(lx, ly), pk(lz, lw));
}
#define LDSM_X4(r, a) \
    asm volatile("ldmatrix.sync.aligned.m8n8.x4.shared.b16 {%0,%1,%2,%3}, [%4];" \
        : "=r"((r)[0]), "=r"((r)[1]), "=r"((r)[2]), "=r"((r)[3]) : "r"(a))
#define LDSM_X2(r, a) \
    asm volatile("ldmatrix.sync.aligned.m8n8.x2.shared.b16 {%0,%1}, [%2];" \
        : "=r"((r)[0]), "=r"((r)[1]) : "r"(a))
__device__ __forceinline__ void mma_bf16(float* c, const uint32_t* a, const uint32_t* b) {
    asm volatile("mma.sync.aligned.m16n8k16.row.col.f32.bf16.bf16.f32 "
        "{%0,%1,%2,%3}, {%4,%5,%6,%7}, {%8,%9}, {%0,%1,%2,%3};"
        : "+f"(c[0]), "+f"(c[1]), "+f"(c[2]), "+f"(c[3])
        : "r"(a[0]), "r"(a[1]), "r"(a[2]), "r"(a[3]), "r"(b[0]), "r"(b[1]));
}

// ================= HMMA GEMM =================
// C[M x Nc] = A[M x K] @ Bt[Nc x K]^T + bias; optional fused BN col-stats.
// bf16 hi/lo 3-product split, fp32 accumulate.
#define TM 128
#define TN 128
#define TK 32
#define PITCH 40                      // bf16 elems per smem row (80B, conflict-free)
#define A_LO_B 10240                  // byte offsets within a stage
#define B_HI_B 20480
#define B_LO_B 30720
#define STAGE_B 40960
#define GEMM_SMEM (2 * STAGE_B)

__global__ void __launch_bounds__(256, 1) k_tgemm(
    const float* __restrict__ A, int lda,
    const float* __restrict__ Bt, int ldb,
    const float* __restrict__ bias,
    float* __restrict__ C, int ldc,
    int M, int Nc, int K,
    float* __restrict__ stats, int do_stats)
{
    extern __shared__ char smem[];
    uint32_t sbase = smem_u32(smem);
    int tid = threadIdx.x, wid = tid >> 5, lane = tid & 31;
    int row0 = blockIdx.y * TM;
    int col0 = blockIdx.x * TN;
    int wm = wid & 1, wn = wid >> 1;       // warp tile: rows wm*64, cols wn*32

    float acc[4][4][4];
#pragma unroll
    for (int i = 0; i < 4; i++)
#pragma unroll
        for (int j = 0; j < 4; j++)
#pragma unroll
            for (int q = 0; q < 4; q++) acc[i][j][q] = 0.f;

    int nt = (K + TK - 1) / TK;
    float4 pa[4], pb[4];
    const float4 z4 = make_float4(0.f, 0.f, 0.f, 0.f);

#define LDTILE(T) do { \
    int kt = (T) * TK; \
    _Pragma("unroll") \
    for (int i2 = 0; i2 < 4; i2++) { \
        int slot = tid + i2 * 256; \
        int r = slot >> 3, k4 = slot & 7; \
        int gk = kt + k4 * 4; \
        int gm = row0 + r, gn = col0 + r; \
        bool kok = (gk + 4 <= K); \
        pa[i2] = (kok && gm < M)  ? *(const float4*)(A  + (size_t)gm * lda + gk) : z4; \
        pb[i2] = (kok && gn < Nc) ? *(const float4*)(Bt + (size_t)gn * ldb + gk) : z4; \
    } } while (0)

#define STTILE(BUF) do { \
    char* st = smem + (BUF) * STAGE_B; \
    _Pragma("unroll") \
    for (int i2 = 0; i2 < 4; i2++) { \
        int slot = tid + i2 * 256; \
        int r = slot >> 3, k4 = slot & 7; \
        uint32_t off = (uint32_t)(r * PITCH + k4 * 4) * 2; \
        uint2 hi, lo; \
        cvt4(pa[i2], hi, lo); \
        *(uint2*)(st + off) = hi; \
        *(uint2*)(st + A_LO_B + off) = lo; \
        cvt4(pb[i2], hi, lo); \
        *(uint2*)(st + B_HI_B + off) = hi; \
        *(uint2*)(st + B_LO_B + off) = lo; \
    } } while (0)

    LDTILE(0);
    STTILE(0);
    __syncthreads();

    int a_r = lane & 15;                   // A ldmatrix row within 16
    int a_c = (lane >> 4) << 3;            // 0 or 8
    int b_r = lane & 7;
    int b_c = ((lane >> 3) & 1) << 3;

    for (int t = 0; t < nt; t++) {
        int buf = t & 1;
        bool more = (t + 1 < nt);
        if (more) LDTILE(t + 1);

        uint32_t sA = sbase + buf * STAGE_B;
        uint32_t sB = sA + B_HI_B;
#pragma unroll
        for (int kk = 0; kk < TK; kk += 16) {
            uint32_t ah[4][4], al[4][4], bh[4][2], bl[4][2];
#pragma unroll
            for (int i = 0; i < 4; i++) {
                uint32_t ad = sA + (uint32_t)((wm * 64 + i * 16 + a_r) * PITCH + kk + a_c) * 2;
                LDSM_X4(ah[i], ad);
                LDSM_X4(al[i], ad + A_LO_B);
            }
#pragma unroll
            for (int j = 0; j < 4; j++) {
                uint32_t bd = sB + (uint32_t)((wn * 32 + j * 8 + b_r) * PITCH + kk + b_c) * 2;
                LDSM_X2(bh[j], bd);
                LDSM_X2(bl[j], bd + A_LO_B);
            }
#pragma unroll
            for (int i = 0; i < 4; i++)
#pragma unroll
                for (int j = 0; j < 4; j++) {
                    mma_bf16(acc[i][j], ah[i], bh[j]);
                    mma_bf16(acc[i][j], ah[i], bl[j]);
                    mma_bf16(acc[i][j], al[i], bh[j]);
                }
        }
        if (more) STTILE(buf ^ 1);
        __syncthreads();
    }

    // ---- epilogue: bias + store + masked values for stats ----
    int g = lane >> 2, t4 = lane & 3;
#pragma unroll
    for (int i = 0; i < 4; i++) {
        int r0c = row0 + wm * 64 + i * 16 + g;
        bool rv0 = (r0c < M), rv1 = (r0c + 8 < M);
#pragma unroll
        for (int j = 0; j < 4; j++) {
            int c0c = col0 + wn * 32 + j * 8 + t4 * 2;
            bool cv0 = (c0c < Nc), cv1 = (c0c + 1 < Nc);
            float b0 = cv0 ? bias[c0c] : 0.f;
            float b1 = cv1 ? bias[c0c + 1] : 0.f;
            float v0 = acc[i][j][0] + b0, v1 = acc[i][j][1] + b1;
            float v2 = acc[i][j][2] + b0, v3 = acc[i][j][3] + b1;
            if (rv0 && cv0) C[(size_t)r0c * ldc + c0c] = v0;
            if (rv0 && cv1) C[(size_t)r0c * ldc + c0c + 1] = v1;
            if (rv1 && cv0) C[(size_t)(r0c + 8) * ldc + c0c] = v2;
            if (rv1 && cv1) C[(size_t)(r0c + 8) * ldc + c0c + 1] = v3;
            acc[i][j][0] = (rv0 && cv0) ? v0 : 0.f;
            acc[i][j][1] = (rv0 && cv1) ? v1 : 0.f;
            acc[i][j][2] = (rv1 && cv0) ? v2 : 0.f;
            acc[i][j][3] = (rv1 && cv1) ? v3 : 0.f;
        }
    }
    if (do_stats) {
#pragma unroll
        for (int j = 0; j < 4; j++) {
            float se = 0.f, so = 0.f, qe = 0.f, qo = 0.f;
#pragma unroll
            for (int i = 0; i < 4; i++) {
                float v0 = acc[i][j][0], v1 = acc[i][j][1];
                float v2 = acc[i][j][2], v3 = acc[i][j][3];
                se += v0 + v2; so += v1 + v3;
                qe += v0 * v0 + v2 * v2; qo += v1 * v1 + v3 * v3;
            }
#pragma unroll
            for (int off = 4; off < 32; off <<= 1) {
                se += __shfl_xor_sync(0xffffffffu, se, off);
                so += __shfl_xor_sync(0xffffffffu, so, off);
                qe += __shfl_xor_sync(0xffffffffu, qe, off);
                qo += __shfl_xor_sync(0xffffffffu, qo, off);
            }
            if (lane < 4) {
                int ce = col0 + wn * 32 + j * 8 + lane * 2;
                if (ce < Nc)     { atomicAdd(&stats[ce], se);     atomicAdd(&stats[Nc + ce], qe); }
                if (ce + 1 < Nc) { atomicAdd(&stats[ce + 1], so); atomicAdd(&stats[Nc + ce + 1], qo); }
            }
        }
    }
#undef LDTILE
#undef STTILE
}

// ================= transpose (batched, 32x32 tiles) =================
__global__ void k_transpose(const float* __restrict__ in, float* __restrict__ out, int R, int Cc) {
    __shared__ float t[32][33];
    int b = blockIdx.z;
    const float* I = in + (size_t)b * R * Cc;
    float* O = out + (size_t)b * R * Cc;
    int r0 = blockIdx.y * 32, c0 = blockIdx.x * 32;
    int c = c0 + threadIdx.x;
#pragma unroll
    for (int i = 0; i < 32; i += 8) {
        int r = r0 + threadIdx.y + i;
        if (r < R && c < Cc) t[threadIdx.y + i][threadIdx.x] = I[(size_t)r * Cc + c];
    }
    __syncthreads();
    int cc = r0 + threadIdx.x;
#pragma unroll
    for (int i = 0; i < 32; i += 8) {
        int rr = c0 + threadIdx.y + i;
        if (rr < Cc && cc < R) O[(size_t)rr * R + cc] = t[threadIdx.x][threadIdx.y + i];
    }
}

// ================= elementwise =================
__global__ void k_zero(float* p, int n) {
    int i = blockIdx.x * blockDim.x + threadIdx.x;
    if (i < n) p[i] = 0.f;
}
__global__ void k_zero_u(unsigned* p, int n) {
    int i = blockIdx.x * blockDim.x + threadIdx.x;
    if (i < n) p[i] = 0u;
}
__global__ void k_init_h4(const float4* __restrict__ atom_emb, const int* __restrict__ x_idx,
                          float4* __restrict__ h) {
    long i = (long)blockIdx.x * blockDim.x + threadIdx.x;
    const int C4 = DD / 4;
    long total = (long)NN * C4;
    if (i >= total) return;
    int n = (int)(i / C4);
    int d = (int)(i - (long)n * C4);
    h[i] = atom_emb[(size_t)x_idx[n] * C4 + d];
}
__global__ void k_init_z4(const float4* __restrict__ h, const float* __restrict__ epsp,
                          float4* __restrict__ z) {
    long i = (long)blockIdx.x * blockDim.x + threadIdx.x;
    long total = (long)NN * (DD / 4);
    if (i >= total) return;
    float e = 1.f + *epsp;
    float4 v = h[i];
    z[i] = make_float4(e * v.x, e * v.y, e * v.z, e * v.w);
}
__global__ void k_edge4(const float4* __restrict__ h, const float4* __restrict__ ee,
                        const int* __restrict__ attr, const int* __restrict__ ei,
                        float* __restrict__ z) {
    long i = (long)blockIdx.x * blockDim.x + threadIdx.x;
    const int C4 = DD / 4;
    long total = (long)EE * C4;
    if (i >= total) return;
    int e = (int)(i / C4);
    int q = (int)(i - (long)e * C4);
    int src = ei[e];
    int dst = ei[EE + e];
    float4 a = h[(size_t)src * C4 + q];
    float4 b = ee[(size_t)attr[e] * C4 + q];
    float m0 = a.x + b.x, m1 = a.y + b.y, m2 = a.z + b.z, m3 = a.w + b.w;
    float* zp = z + (size_t)dst * DD + q * 4;
    if (m0 > 0.f) atomicAdd(zp + 0, m0);
    if (m1 > 0.f) atomicAdd(zp + 1, m1);
    if (m2 > 0.f) atomicAdd(zp + 2, m2);
    if (m3 > 0.f) atomicAdd(zp + 3, m3);
}
__global__ void k_bn_final(const float* __restrict__ sums, float invM, int C,
                           const float* __restrict__ gamma, const float* __restrict__ beta,
                           float* __restrict__ scale, float* __restrict__ shift) {
    int c = blockIdx.x * blockDim.x + threadIdx.x;
    if (c >= C) return;
    float mean = sums[c] * invM;
    float var  = sums[C + c] * invM - mean * mean;
    float istd = rsqrtf(var + 1e-5f);
    float sc = istd * gamma[c];
    scale[c] = sc;
    shift[c] = beta[c] - mean * sc;
}
// mode 0: X=relu(bn); 1: res+=relu(bn); 2: res+=bn; 3: X=gelu(bn)
__global__ void k_bn_apply4(float4* __restrict__ X, float4* __restrict__ res,
                            const float4* __restrict__ scale, const float4* __restrict__ shift,
                            long total4, int C4, int mode) {
    long i = (long)blockIdx.x * blockDim.x + threadIdx.x;
    if (i >= total4) return;
    int c = (int)(i % C4);
    float4 x = X[i], sc = scale[c], sh = shift[c];
    float v0 = x.x * sc.x + sh.x, v1 = x.y * sc.y + sh.y;
    float v2 = x.z * sc.z + sh.z, v3 = x.w * sc.w + sh.w;
    if (mode == 0) {
        X[i] = make_float4(fmaxf(v0, 0.f), fmaxf(v1, 0.f), fmaxf(v2, 0.f), fmaxf(v3, 0.f));
    } else if (mode == 1) {
        float4 r = res[i];
        res[i] = make_float4(r.x + fmaxf(v0, 0.f), r.y + fmaxf(v1, 0.f),
                             r.z + fmaxf(v2, 0.f), r.w + fmaxf(v3, 0.f));
    } else if (mode == 2) {
        float4 r = res[i];
        res[i] = make_float4(r.x + v0, r.y + v1, r.z + v2, r.w + v3);
    } else {
        const float k = 0.70710678118654752f;
        X[i] = make_float4(0.5f * v0 * (1.f + erff(v0 * k)), 0.5f * v1 * (1.f + erff(v1 * k)),
                           0.5f * v2 * (1.f + erff(v2 * k)), 0.5f * v3 * (1.f + erff(v3 * k)));
    }
}
__device__ __forceinline__ unsigned enc_f(float x) {
    unsigned u = __float_as_uint(x);
    return (u & 0x80000000u) ? ~u : (u | 0x80000000u);
}
__global__ void k_segmax(const float* __restrict__ h, const int* __restrict__ batch,
                         unsigned* __restrict__ hg) {
    long i = (long)blockIdx.x * blockDim.x + threadIdx.x;
    long total = (long)NN * DD;
    if (i >= total) return;
    int n = (int)(i / DD);
    int d = (int)(i - (long)n * DD);
    atomicMax(&hg[(size_t)batch[n] * DD + d], enc_f(h[i]));
}
__global__ void k_decode_silu(const unsigned* __restrict__ hg, float* __restrict__ s, int total) {
    int i = blockIdx.x * blockDim.x + threadIdx.x;
    if (i >= total) return;
    unsigned u = hg[i];
    u = (u & 0x80000000u) ? (u & 0x7fffffffu) : ~u;
    float x = __uint_as_float(u);
    s[i] = x / (1.f + expf(-x));
}
__global__ void k_split(const float* __restrict__ d, float* __restrict__ out,
                        float* __restrict__ mu, long offS) {
    long i = (long)blockIdx.x * blockDim.x + threadIdx.x;
    long total = (long)GG * HH;
    if (i >= total) return;
    int g = (int)(i / HH);
    int c = (int)(i - (long)g * HH);
    float v = d[i];
    if (c < DD) {
        out[(size_t)g * DD + c] = v;
        mu[(size_t)g * DD + c]  = v;
    } else {
        float sp = fmaxf(v, 0.f) + log1pf(expf(-fabsf(v))) + 1e-7f;
        out[offS + (size_t)g * DD + (c - DD)] = sp;
    }
}

// ================= host side =================
static void tgemm(const float* A, int lda, const float* Bt, int ldb, const float* bias,
                  float* C, int ldc, int M, int Nc, int K, float* stats, int do_stats) {
    dim3 gr((Nc + TN - 1) / TN, (M + TM - 1) / TM);
    k_tgemm<<<gr, 256, GEMM_SMEM>>>(A, lda, Bt, ldb, bias, C, ldc, M, Nc, K, stats, do_stats);
}
static void transpose(const float* in, float* out, int R, int C, int B) {
    dim3 bl(32, 8), gr((C + 31) / 32, (R + 31) / 32, B);
    k_transpose<<<gr, bl>>>(in, out, R, C);
}

extern "C" void kernel_launch(void* const* d_in, const int* in_sizes, int n_in,
                              void* d_out, int out_size) {
    const float* atom_emb   = (const float*)d_in[0];
    const float* edge_emb   = (const float*)d_in[1];
    const float* eps        = (const float*)d_in[2];
    const float* conv_w1    = (const float*)d_in[3];
    const float* conv_b1    = (const float*)d_in[4];
    const float* conv_bn1_g = (const float*)d_in[5];
    const float* conv_bn1_b = (const float*)d_in[6];
    const float* conv_w2    = (const float*)d_in[7];
    const float* conv_b2    = (const float*)d_in[8];
    const float* bn_g       = (const float*)d_in[9];
    const float* bn_b       = (const float*)d_in[10];
    const float* dist_w     = (const float*)d_in[11];
    const float* dist_b     = (const float*)d_in[12];
    const float* dec_w1     = (const float*)d_in[13];
    const float* dec_b1     = (const float*)d_in[14];
    const float* dec_bn_g   = (const float*)d_in[15];
    const float* dec_bn_b   = (const float*)d_in[16];
    const float* dec_w2     = (const float*)d_in[17];
    const float* dec_b2     = (const float*)d_in[18];
    const int*   x_idx      = (const int*)d_in[19];
    const int*   edge_attr  = (const int*)d_in[20];
    const int*   edge_index = (const int*)d_in[21];
    const int*   batch      = (const int*)d_in[22];
    float* out = (float*)d_out;

    cudaFuncSetAttribute(k_tgemm, cudaFuncAttributeMaxDynamicSharedMemorySize, GEMM_SMEM);

    float *h, *z, *y, *stats, *scale, *shift, *s, *dbuf, *mu, *dz;
    float *w1t, *w2t, *dwt, *d1t, *d2t;
    unsigned* hg;
    cudaGetSymbolAddress((void**)&h,     g_h);
    cudaGetSymbolAddress((void**)&z,     g_z);
    cudaGetSymbolAddress((void**)&y,     g_y);
    cudaGetSymbolAddress((void**)&stats, g_stats);
    cudaGetSymbolAddress((void**)&scale, g_scale);
    cudaGetSymbolAddress((void**)&shift, g_shift);
    cudaGetSymbolAddress((void**)&hg,    g_hg);
    cudaGetSymbolAddress((void**)&s,     g_s);
    cudaGetSymbolAddress((void**)&dbuf,  g_d);
    cudaGetSymbolAddress((void**)&mu,    g_mu);
    cudaGetSymbolAddress((void**)&dz,    g_dz);
    cudaGetSymbolAddress((void**)&w1t,   g_w1t);
    cudaGetSymbolAddress((void**)&w2t,   g_w2t);
    cudaGetSymbolAddress((void**)&dwt,   g_dwt);
    cudaGetSymbolAddress((void**)&d1t,   g_d1t);
    cudaGetSymbolAddress((void**)&d2t,   g_d2t);

    // transpose weights once per call
    transpose(conv_w1, w1t, DD, HH, LL);
    transpose(conv_w2, w2t, HH, DD, LL);
    transpose(dist_w,  dwt, DD, HH, 1);
    transpose(dec_w1,  d1t, DD, DECH, 6);
    transpose(dec_w2,  d2t, DECH, MAXO, 6);

    const long ND  = (long)NN * DD;
    const long ND4 = ND / 4;
    const long NH4 = (long)NN * HH / 4;
    const long ED4 = (long)EE * DD / 4;

    k_init_h4<<<(int)((ND4 + 255) / 256), 256>>>((const float4*)atom_emb, x_idx, (float4*)h);

    for (int l = 0; l < LL; l++) {
        k_init_z4<<<(int)((ND4 + 255) / 256), 256>>>((const float4*)h, eps + l, (float4*)z);
        k_edge4<<<(int)((ED4 + 255) / 256), 256>>>((const float4*)h,
                 (const float4*)(edge_emb + (size_t)l * 5 * DD), edge_attr, edge_index, z);
        // y = z @ w1 + b1 ; fused stats ; relu(bn)
        k_zero<<<(2 * HH + 255) / 256, 256>>>(stats, 2 * HH);
        tgemm(z, DD, w1t + (size_t)l * HH * DD, DD, conv_b1 + (size_t)l * HH,
              y, HH, NN, HH, DD, stats, 1);
        k_bn_final<<<(HH + 255) / 256, 256>>>(stats, 1.f / (float)NN, HH,
              conv_bn1_g + (size_t)l * HH, conv_bn1_b + (size_t)l * HH, scale, shift);
        k_bn_apply4<<<(int)((NH4 + 255) / 256), 256>>>((float4*)y, nullptr,
              (const float4*)scale, (const float4*)shift, NH4, HH / 4, 0);
        // z = y @ w2 + b2 ; fused stats ; h += act(bn)
        k_zero<<<(2 * DD + 255) / 256, 256>>>(stats, 2 * DD);
        tgemm(y, HH, w2t + (size_t)l * DD * HH, HH, conv_b2 + (size_t)l * DD,
              z, DD, NN, DD, HH, stats, 1);
        k_bn_final<<<(DD + 255) / 256, 256>>>(stats, 1.f / (float)NN, DD,
              bn_g + (size_t)l * DD, bn_b + (size_t)l * DD, scale, shift);
        k_bn_apply4<<<(int)((ND4 + 255) / 256), 256>>>((float4*)z, (float4*)h,
              (const float4*)scale, (const float4*)shift, ND4, DD / 4, (l < LL - 1) ? 1 : 2);
    }

    // pooling
    int GD = GG * DD;
    k_zero_u<<<(GD + 255) / 256, 256>>>(hg, GD);
    k_segmax<<<(int)((ND + 255) / 256), 256>>>(h, batch, hg);
    k_decode_silu<<<(GD + 255) / 256, 256>>>(hg, s, GD);

    // d = silu(h_graph) @ dist_w + dist_b
    tgemm(s, DD, dwt, DD, dist_b, dbuf, HH, GG, HH, DD, stats, 0);

    const long OFF_SG = (long)GG * DD;
    k_split<<<(int)(((long)GG * HH + 255) / 256), 256>>>(dbuf, out, mu, OFF_SG);

    const long OFF_O0   = 2L * GG * DD;
    const long OFF_GENE = OFF_O0 + (long)GG * 1024;
    const long OFF_CELL = OFF_GENE + (long)GG * 1973;
    const long OFF_O5   = OFF_CELL + (long)GG * 2749;
    const int  dims[6] = {1024, 1111, 862, 1783, 966, 978};
    const long base[6] = {OFF_O0, OFF_GENE, OFF_GENE + 1111, OFF_CELL, OFF_CELL + 1783, OFF_O5};
    const int  ldcs[6] = {1024, 1973, 1973, 2749, 2749, 978};

    const long GDH4 = (long)GG * DECH / 4;
    for (int i = 0; i < 6; i++) {
        k_zero<<<(2 * DECH + 255) / 256, 256>>>(stats, 2 * DECH);
        tgemm(mu, DD, d1t + (size_t)i * DECH * DD, DD, dec_b1 + (size_t)i * DECH,
              dz, DECH, GG, DECH, DD, stats, 1);
        k_bn_final<<<(DECH + 255) / 256, 256>>>(stats, 1.f / (float)GG, DECH,
              dec_bn_g + (size_t)i * DECH, dec_bn_b + (size_t)i * DECH, scale, shift);
        k_bn_apply4<<<(int)((GDH4 + 255) / 256), 256>>>((float4*)dz, nullptr,
              (const float4*)scale, (const float4*)shift, GDH4, DECH / 4, 3);
        tgemm(dz, DECH, d2t + (size_t)i * MAXO * DECH, DECH, dec_b2 + (size_t)i * MAXO,
              out + base[i], ldcs[i], GG, dims[i], DECH, stats, 0);
    }
}

// round 5
// speedup vs baseline: 2.9400x; 1.0479x over previous
#include <cuda_runtime.h>
#include <cuda_bf16.h>
#include <math.h>
#include <stdint.h>

#define NN 100000
#define EE 200000
#define GG 4096
#define DD 300
#define HH 600
#define LL 5
#define DECH 1200
#define MAXO 1783
// padded K dims (multiple of 32; x2 bytes multiple of 16)
#define KPD 320
#define KPH 608
#define KPDEC 1216

// ---------------- scratch (device globals) ----------------
__device__ float g_h [(size_t)NN*DD];
__device__ float g_z [(size_t)NN*DD];
__device__ float g_y [(size_t)NN*HH];
__device__ float g_stats[2*DECH];
__device__ float g_scale[DECH];
__device__ float g_shift[DECH];
__device__ unsigned g_hg[(size_t)GG*DD];
__device__ float g_d [(size_t)GG*HH];
__device__ float g_dz[(size_t)GG*DECH];
// bf16 hi/lo activation planes
__device__ __nv_bfloat16 g_zh[(size_t)NN*KPD],  g_zl[(size_t)NN*KPD];
__device__ __nv_bfloat16 g_yh[(size_t)NN*KPH],  g_yl[(size_t)NN*KPH];
__device__ __nv_bfloat16 g_sh[(size_t)GG*KPD],  g_sl[(size_t)GG*KPD];
__device__ __nv_bfloat16 g_muh[(size_t)GG*KPD], g_mul[(size_t)GG*KPD];
__device__ __nv_bfloat16 g_dzh[(size_t)GG*KPDEC], g_dzl[(size_t)GG*KPDEC];
// bf16 hi/lo transposed weights
__device__ __nv_bfloat16 g_w1th[(size_t)LL*HH*KPD],   g_w1tl[(size_t)LL*HH*KPD];
__device__ __nv_bfloat16 g_w2th[(size_t)LL*DD*KPH],   g_w2tl[(size_t)LL*DD*KPH];
__device__ __nv_bfloat16 g_dwth[(size_t)HH*KPD],      g_dwtl[(size_t)HH*KPD];
__device__ __nv_bfloat16 g_d1th[(size_t)6*DECH*KPD],  g_d1tl[(size_t)6*DECH*KPD];
__device__ __nv_bfloat16 g_d2th[(size_t)6*MAXO*KPDEC], g_d2tl[(size_t)6*MAXO*KPDEC];

// ================= helpers =================
__device__ __forceinline__ uint32_t smem_u32(const void* p) {
    uint32_t a;
    asm("{ .reg .u64 t; cvta.to.shared.u64 t, %1; cvt.u32.u64 %0, t; }" : "=r"(a) : "l"(p));
    return a;
}
__device__ __forceinline__ void split_bf(float v, __nv_bfloat16& h, __nv_bfloat16& l) {
    h = __float2bfloat16(v);
    l = __float2bfloat16(v - __bfloat162float(h));
}
#define LDSM_X4(r, a) \
    asm volatile("ldmatrix.sync.aligned.m8n8.x4.shared.b16 {%0,%1,%2,%3}, [%4];" \
        : "=r"((r)[0]), "=r"((r)[1]), "=r"((r)[2]), "=r"((r)[3]) : "r"(a))
#define LDSM_X2(r, a) \
    asm volatile("ldmatrix.sync.aligned.m8n8.x2.shared.b16 {%0,%1}, [%2];" \
        : "=r"((r)[0]), "=r"((r)[1]) : "r"(a))
__device__ __forceinline__ void mma_bf16(float* c, const uint32_t* a, const uint32_t* b) {
    asm volatile("mma.sync.aligned.m16n8k16.row.col.f32.bf16.bf16.f32 "
        "{%0,%1,%2,%3}, {%4,%5,%6,%7}, {%8,%9}, {%0,%1,%2,%3};"
        : "+f"(c[0]), "+f"(c[1]), "+f"(c[2]), "+f"(c[3])
        : "r"(a[0]), "r"(a[1]), "r"(a[2]), "r"(a[3]), "r"(b[0]), "r"(b[1]));
}
__device__ __forceinline__ void cpa16(uint32_t dst, const void* src, int bytes) {
    asm volatile("cp.async.cg.shared.global [%0], [%1], 16, %2;"
        :: "r"(dst), "l"(src), "r"(bytes) : "memory");
}
#define CPA_COMMIT() asm volatile("cp.async.commit_group;" ::: "memory")
#define CPA_WAIT1()  asm volatile("cp.async.wait_group 1;" ::: "memory")

// ================= HMMA GEMM =================
// C[M x Nc] = A[M x Kp] @ Bt[Nc x Kp]^T + bias; A,B given as bf16 hi/lo planes.
// 3-product hi/lo split, fp32 accumulate, cp.async 3-stage pipeline.
#define TM 128
#define TN 128
#define TK 32
#define PITCH 40                 // bf16 elems per smem row (80B)
#define ARR_B 10240              // bytes per sub-array (128 rows x 80B)
#define STAGE_B 40960
#define GEMM_SMEM (3 * STAGE_B)

__global__ void __launch_bounds__(256, 1) k_tgemm(
    const __nv_bfloat16* __restrict__ Ah, const __nv_bfloat16* __restrict__ Al, int lda,
    const __nv_bfloat16* __restrict__ Bh, const __nv_bfloat16* __restrict__ Bl, int ldb,
    const float* __restrict__ bias,
    float* __restrict__ C, int ldc,
    int M, int Nc, int Kp,
    float* __restrict__ stats, int do_stats)
{
    extern __shared__ char smem[];
    uint32_t sbase = smem_u32(smem);
    int tid = threadIdx.x, wid = tid >> 5, lane = tid & 31;
    int row0 = blockIdx.y * TM;
    int col0 = blockIdx.x * TN;
    int wm = wid & 1, wn = wid >> 1;

    float acc[4][4][4];
#pragma unroll
    for (int i = 0; i < 4; i++)
#pragma unroll
        for (int j = 0; j < 4; j++)
#pragma unroll
            for (int q = 0; q < 4; q++) acc[i][j][q] = 0.f;

    int nt = Kp / TK;

#define LOADST(T, BUF) do { \
    int kt = (T) * TK; \
    uint32_t sst = sbase + (uint32_t)(BUF) * STAGE_B; \
    _Pragma("unroll") \
    for (int q = 0; q < 8; q++) { \
        int w = tid + (q & 1) * 256; \
        int r = w >> 2, k8 = w & 3; \
        int arr = q >> 1; \
        uint32_t dst = sst + (uint32_t)(arr * ARR_B + r * 80 + k8 * 16); \
        const __nv_bfloat16* base; int gr, ld, lim; \
        if (arr == 0)      { base = Ah; gr = row0 + r; ld = lda; lim = M; } \
        else if (arr == 1) { base = Al; gr = row0 + r; ld = lda; lim = M; } \
        else if (arr == 2) { base = Bh; gr = col0 + r; ld = ldb; lim = Nc; } \
        else               { base = Bl; gr = col0 + r; ld = ldb; lim = Nc; } \
        int ok = (gr < lim) ? 16 : 0; \
        int grc = (gr < lim) ? gr : 0; \
        cpa16(dst, base + (size_t)grc * ld + kt + k8 * 8, ok); \
    } } while (0)

    LOADST(0, 0); CPA_COMMIT();
    if (nt > 1) { LOADST(1, 1); }
    CPA_COMMIT();

    int a_r = lane & 15;
    int a_c = (lane >> 4) << 3;
    int b_r = lane & 7;
    int b_c = ((lane >> 3) & 1) << 3;

    for (int t = 0; t < nt; t++) {
        CPA_WAIT1();
        __syncthreads();
        int buf = t % 3;
        uint32_t sA = sbase + (uint32_t)buf * STAGE_B;
        uint32_t sB = sA + 2 * ARR_B;
#pragma unroll
        for (int kk = 0; kk < TK; kk += 16) {
            uint32_t ah[4][4], al[4][4], bh[4][2], bl[4][2];
#pragma unroll
            for (int i = 0; i < 4; i++) {
                uint32_t ad = sA + (uint32_t)((wm * 64 + i * 16 + a_r) * PITCH + kk + a_c) * 2;
                LDSM_X4(ah[i], ad);
                LDSM_X4(al[i], ad + ARR_B);
            }
#pragma unroll
            for (int j = 0; j < 4; j++) {
                uint32_t bd = sB + (uint32_t)((wn * 32 + j * 8 + b_r) * PITCH + kk + b_c) * 2;
                LDSM_X2(bh[j], bd);
                LDSM_X2(bl[j], bd + ARR_B);
            }
#pragma unroll
            for (int i = 0; i < 4; i++)
#pragma unroll
                for (int j = 0; j < 4; j++) {
                    mma_bf16(acc[i][j], ah[i], bh[j]);
                    mma_bf16(acc[i][j], ah[i], bl[j]);
                    mma_bf16(acc[i][j], al[i], bh[j]);
                }
        }
        if (t + 2 < nt) { LOADST(t + 2, (t + 2) % 3); }
        CPA_COMMIT();
    }
#undef LOADST

    // ---- epilogue: bias + store + stats ----
    int g = lane >> 2, t4 = lane & 3;
#pragma unroll
    for (int i = 0; i < 4; i++) {
        int r0c = row0 + wm * 64 + i * 16 + g;
        bool rv0 = (r0c < M), rv1 = (r0c + 8 < M);
#pragma unroll
        for (int j = 0; j < 4; j++) {
            int c0c = col0 + wn * 32 + j * 8 + t4 * 2;
            bool cv0 = (c0c < Nc), cv1 = (c0c + 1 < Nc);
            float b0 = cv0 ? bias[c0c] : 0.f;
            float b1 = cv1 ? bias[c0c + 1] : 0.f;
            float v0 = acc[i][j][0] + b0, v1 = acc[i][j][1] + b1;
            float v2 = acc[i][j][2] + b0, v3 = acc[i][j][3] + b1;
            if (rv0 && cv0) C[(size_t)r0c * ldc + c0c] = v0;
            if (rv0 && cv1) C[(size_t)r0c * ldc + c0c + 1] = v1;
            if (rv1 && cv0) C[(size_t)(r0c + 8) * ldc + c0c] = v2;
            if (rv1 && cv1) C[(size_t)(r0c + 8) * ldc + c0c + 1] = v3;
            acc[i][j][0] = (rv0 && cv0) ? v0 : 0.f;
            acc[i][j][1] = (rv0 && cv1) ? v1 : 0.f;
            acc[i][j][2] = (rv1 && cv0) ? v2 : 0.f;
            acc[i][j][3] = (rv1 && cv1) ? v3 : 0.f;
        }
    }
    if (do_stats) {
#pragma unroll
        for (int j = 0; j < 4; j++) {
            float se = 0.f, so = 0.f, qe = 0.f, qo = 0.f;
#pragma unroll
            for (int i = 0; i < 4; i++) {
                float v0 = acc[i][j][0], v1 = acc[i][j][1];
                float v2 = acc[i][j][2], v3 = acc[i][j][3];
                se += v0 + v2; so += v1 + v3;
                qe += v0 * v0 + v2 * v2; qo += v1 * v1 + v3 * v3;
            }
#pragma unroll
            for (int off = 4; off < 32; off <<= 1) {
                se += __shfl_xor_sync(0xffffffffu, se, off);
                so += __shfl_xor_sync(0xffffffffu, so, off);
                qe += __shfl_xor_sync(0xffffffffu, qe, off);
                qo += __shfl_xor_sync(0xffffffffu, qo, off);
            }
            if (lane < 4) {
                int ce = col0 + wn * 32 + j * 8 + lane * 2;
                if (ce < Nc)     { atomicAdd(&stats[ce], se);     atomicAdd(&stats[Nc + ce], qe); }
                if (ce + 1 < Nc) { atomicAdd(&stats[ce + 1], so); atomicAdd(&stats[Nc + ce + 1], qo); }
            }
        }
    }
}

// ============ weight transpose + hi/lo convert (batched) ============
// in: [K x N] fp32 (batch-major); out: [N x Kp] bf16 hi/lo, pads zeroed.
__global__ void k_wcvt(const float* __restrict__ in,
                       __nv_bfloat16* __restrict__ hi, __nv_bfloat16* __restrict__ lo,
                       int K, int N, int Kp) {
    __shared__ float t[32][33];
    int b = blockIdx.z;
    const float* I = in + (size_t)b * K * N;
    __nv_bfloat16* H = hi + (size_t)b * N * Kp;
    __nv_bfloat16* L = lo + (size_t)b * N * Kp;
    int r0 = blockIdx.y * 32, c0 = blockIdx.x * 32;   // r: K dim, c: N dim
    int c = c0 + threadIdx.x;
#pragma unroll
    for (int i = 0; i < 32; i += 8) {
        int r = r0 + threadIdx.y + i;
        t[threadIdx.y + i][threadIdx.x] = (r < K && c < N) ? I[(size_t)r * N + c] : 0.f;
    }
    __syncthreads();
    int k = r0 + threadIdx.x;
#pragma unroll
    for (int i = 0; i < 32; i += 8) {
        int n = c0 + threadIdx.y + i;
        if (n < N && k < Kp) {
            float v = t[threadIdx.x][threadIdx.y + i];
            __nv_bfloat16 h, l; split_bf(v, h, l);
            H[(size_t)n * Kp + k] = h;
            L[(size_t)n * Kp + k] = l;
        }
    }
}

// generic fp32 -> padded bf16 hi/lo
__global__ void k_cvtpad(const float* __restrict__ in,
                         __nv_bfloat16* __restrict__ hi, __nv_bfloat16* __restrict__ lo,
                         long total, int C, int Cp) {
    long i = (long)blockIdx.x * blockDim.x + threadIdx.x;
    if (i >= total) return;
    int n = (int)(i / Cp), c = (int)(i - (long)n * Cp);
    float v = (c < C) ? in[(size_t)n * C + c] : 0.f;
    __nv_bfloat16 h, l; split_bf(v, h, l);
    hi[i] = h; lo[i] = l;
}

// BN apply + activation + hi/lo convert (relu: gelu=0; gelu: gelu=1)
__global__ void k_bnact_cvt(const float* __restrict__ X,
                            const float* __restrict__ scale, const float* __restrict__ shift,
                            __nv_bfloat16* __restrict__ hi, __nv_bfloat16* __restrict__ lo,
                            long total, int C, int Cp, int gelu) {
    long i = (long)blockIdx.x * blockDim.x + threadIdx.x;
    if (i >= total) return;
    int n = (int)(i / Cp), c = (int)(i - (long)n * Cp);
    float r = 0.f;
    if (c < C) {
        float v = X[(size_t)n * C + c] * scale[c] + shift[c];
        r = gelu ? (0.5f * v * (1.f + erff(v * 0.70710678118654752f))) : fmaxf(v, 0.f);
    }
    __nv_bfloat16 h, l; split_bf(r, h, l);
    hi[i] = h; lo[i] = l;
}

// ================= elementwise =================
__global__ void k_zero(float* p, int n) {
    int i = blockIdx.x * blockDim.x + threadIdx.x;
    if (i < n) p[i] = 0.f;
}
__global__ void k_zero_u(unsigned* p, int n) {
    int i = blockIdx.x * blockDim.x + threadIdx.x;
    if (i < n) p[i] = 0u;
}
__global__ void k_init_h4(const float4* __restrict__ atom_emb, const int* __restrict__ x_idx,
                          float4* __restrict__ h) {
    long i = (long)blockIdx.x * blockDim.x + threadIdx.x;
    const int C4 = DD / 4;
    long total = (long)NN * C4;
    if (i >= total) return;
    int n = (int)(i / C4);
    int d = (int)(i - (long)n * C4);
    h[i] = atom_emb[(size_t)x_idx[n] * C4 + d];
}
__global__ void k_init_z4(const float4* __restrict__ h, const float* __restrict__ epsp,
                          float4* __restrict__ z) {
    long i = (long)blockIdx.x * blockDim.x + threadIdx.x;
    long total = (long)NN * (DD / 4);
    if (i >= total) return;
    float e = 1.f + *epsp;
    float4 v = h[i];
    z[i] = make_float4(e * v.x, e * v.y, e * v.z, e * v.w);
}
__global__ void k_edge4(const float4* __restrict__ h, const float4* __restrict__ ee,
                        const int* __restrict__ attr, const int* __restrict__ ei,
                        float* __restrict__ z) {
    long i = (long)blockIdx.x * blockDim.x + threadIdx.x;
    const int C4 = DD / 4;
    long total = (long)EE * C4;
    if (i >= total) return;
    int e = (int)(i / C4);
    int q = (int)(i - (long)e * C4);
    int src = ei[e];
    int dst = ei[EE + e];
    float4 a = h[(size_t)src * C4 + q];
    float4 b = ee[(size_t)attr[e] * C4 + q];
    float m0 = a.x + b.x, m1 = a.y + b.y, m2 = a.z + b.z, m3 = a.w + b.w;
    float* zp = z + (size_t)dst * DD + q * 4;
    if (m0 > 0.f) atomicAdd(zp + 0, m0);
    if (m1 > 0.f) atomicAdd(zp + 1, m1);
    if (m2 > 0.f) atomicAdd(zp + 2, m2);
    if (m3 > 0.f) atomicAdd(zp + 3, m3);
}
__global__ void k_bn_final(const float* __restrict__ sums, float invM, int C,
                           const float* __restrict__ gamma, const float* __restrict__ beta,
                           float* __restrict__ scale, float* __restrict__ shift) {
    int c = blockIdx.x * blockDim.x + threadIdx.x;
    if (c >= C) return;
    float mean = sums[c] * invM;
    float var  = sums[C + c] * invM - mean * mean;
    float istd = rsqrtf(var + 1e-5f);
    float sc = istd * gamma[c];
    scale[c] = sc;
    shift[c] = beta[c] - mean * sc;
}
// mode 1: res += relu(bn); mode 2: res += bn   (fp32 path for z->h)
__global__ void k_bn_apply4(float4* __restrict__ X, float4* __restrict__ res,
                            const float4* __restrict__ scale, const float4* __restrict__ shift,
                            long total4, int C4, int mode) {
    long i = (long)blockIdx.x * blockDim.x + threadIdx.x;
    if (i >= total4) return;
    int c = (int)(i % C4);
    float4 x = X[i], sc = scale[c], sh = shift[c];
    float v0 = x.x * sc.x + sh.x, v1 = x.y * sc.y + sh.y;
    float v2 = x.z * sc.z + sh.z, v3 = x.w * sc.w + sh.w;
    float4 r = res[i];
    if (mode == 1) {
        res[i] = make_float4(r.x + fmaxf(v0, 0.f), r.y + fmaxf(v1, 0.f),
                             r.z + fmaxf(v2, 0.f), r.w + fmaxf(v3, 0.f));
    } else {
        res[i] = make_float4(r.x + v0, r.y + v1, r.z + v2, r.w + v3);
    }
}
__device__ __forceinline__ unsigned enc_f(float x) {
    unsigned u = __float_as_uint(x);
    return (u & 0x80000000u) ? ~u : (u | 0x80000000u);
}
__global__ void k_segmax(const float* __restrict__ h, const int* __restrict__ batch,
                         unsigned* __restrict__ hg) {
    long i = (long)blockIdx.x * blockDim.x + threadIdx.x;
    long total = (long)NN * DD;
    if (i >= total) return;
    int n = (int)(i / DD);
    int d = (int)(i - (long)n * DD);
    atomicMax(&hg[(size_t)batch[n] * DD + d], enc_f(h[i]));
}
// decode pooled max -> silu -> bf16 hi/lo (padded)
__global__ void k_silu_cvt(const unsigned* __restrict__ hg,
                           __nv_bfloat16* __restrict__ hi, __nv_bfloat16* __restrict__ lo,
                           long total, int C, int Cp) {
    long i = (long)blockIdx.x * blockDim.x + threadIdx.x;
    if (i >= total) return;
    int n = (int)(i / Cp), c = (int)(i - (long)n * Cp);
    float r = 0.f;
    if (c < C) {
        unsigned u = hg[(size_t)n * C + c];
        u = (u & 0x80000000u) ? (u & 0x7fffffffu) : ~u;
        float x = __uint_as_float(u);
        r = x / (1.f + expf(-x));
    }
    __nv_bfloat16 h, l; split_bf(r, h, l);
    hi[i] = h; lo[i] = l;
}
__global__ void k_split(const float* __restrict__ d, float* __restrict__ out, long offS) {
    long i = (long)blockIdx.x * blockDim.x + threadIdx.x;
    long total = (long)GG * HH;
    if (i >= total) return;
    int g = (int)(i / HH);
    int c = (int)(i - (long)g * HH);
    float v = d[i];
    if (c < DD) {
        out[(size_t)g * DD + c] = v;
    } else {
        float sp = fmaxf(v, 0.f) + log1pf(expf(-fabsf(v))) + 1e-7f;
        out[offS + (size_t)g * DD + (c - DD)] = sp;
    }
}

// ================= host side =================
static void tgemm(const __nv_bfloat16* Ah, const __nv_bfloat16* Al, int lda,
                  const __nv_bfloat16* Bh, const __nv_bfloat16* Bl, int ldb,
                  const float* bias, float* C, int ldc,
                  int M, int Nc, int Kp, float* stats, int do_stats) {
    dim3 gr((Nc + TN - 1) / TN, (M + TM - 1) / TM);
    k_tgemm<<<gr, 256, GEMM_SMEM>>>(Ah, Al, lda, Bh, Bl, ldb, bias, C, ldc, M, Nc, Kp, stats, do_stats);
}
static void wcvt(const float* in, __nv_bfloat16* hi, __nv_bfloat16* lo,
                 int K, int N, int Kp, int B) {
    dim3 bl(32, 8), gr((N + 31) / 32, (Kp + 31) / 32, B);
    k_wcvt<<<gr, bl>>>(in, hi, lo, K, N, Kp);
}

extern "C" void kernel_launch(void* const* d_in, const int* in_sizes, int n_in,
                              void* d_out, int out_size) {
    const float* atom_emb   = (const float*)d_in[0];
    const float* edge_emb   = (const float*)d_in[1];
    const float* eps        = (const float*)d_in[2];
    const float* conv_w1    = (const float*)d_in[3];
    const float* conv_b1    = (const float*)d_in[4];
    const float* conv_bn1_g = (const float*)d_in[5];
    const float* conv_bn1_b = (const float*)d_in[6];
    const float* conv_w2    = (const float*)d_in[7];
    const float* conv_b2    = (const float*)d_in[8];
    const float* bn_g       = (const float*)d_in[9];
    const float* bn_b       = (const float*)d_in[10];
    const float* dist_w     = (const float*)d_in[11];
    const float* dist_b     = (const float*)d_in[12];
    const float* dec_w1     = (const float*)d_in[13];
    const float* dec_b1     = (const float*)d_in[14];
    const float* dec_bn_g   = (const float*)d_in[15];
    const float* dec_bn_b   = (const float*)d_in[16];
    const float* dec_w2     = (const float*)d_in[17];
    const float* dec_b2     = (const float*)d_in[18];
    const int*   x_idx      = (const int*)d_in[19];
    const int*   edge_attr  = (const int*)d_in[20];
    const int*   edge_index = (const int*)d_in[21];
    const int*   batch      = (const int*)d_in[22];
    float* out = (float*)d_out;

    cudaFuncSetAttribute(k_tgemm, cudaFuncAttributeMaxDynamicSharedMemorySize, GEMM_SMEM);

    float *h, *z, *y, *stats, *scale, *shift, *dbuf, *dz;
    unsigned* hg;
    __nv_bfloat16 *zh, *zl, *yh, *yl, *sh, *sl, *muh, *mul, *dzh, *dzl;
    __nv_bfloat16 *w1th, *w1tl, *w2th, *w2tl, *dwth, *dwtl, *d1th, *d1tl, *d2th, *d2tl;
    cudaGetSymbolAddress((void**)&h,     g_h);
    cudaGetSymbolAddress((void**)&z,     g_z);
    cudaGetSymbolAddress((void**)&y,     g_y);
    cudaGetSymbolAddress((void**)&stats, g_stats);
    cudaGetSymbolAddress((void**)&scale, g_scale);
    cudaGetSymbolAddress((void**)&shift, g_shift);
    cudaGetSymbolAddress((void**)&hg,    g_hg);
    cudaGetSymbolAddress((void**)&dbuf,  g_d);
    cudaGetSymbolAddress((void**)&dz,    g_dz);
    cudaGetSymbolAddress((void**)&zh,    g_zh);   cudaGetSymbolAddress((void**)&zl,  g_zl);
    cudaGetSymbolAddress((void**)&yh,    g_yh);   cudaGetSymbolAddress((void**)&yl,  g_yl);
    cudaGetSymbolAddress((void**)&sh,    g_sh);   cudaGetSymbolAddress((void**)&sl,  g_sl);
    cudaGetSymbolAddress((void**)&muh,   g_muh);  cudaGetSymbolAddress((void**)&mul, g_mul);
    cudaGetSymbolAddress((void**)&dzh,   g_dzh);  cudaGetSymbolAddress((void**)&dzl, g_dzl);
    cudaGetSymbolAddress((void**)&w1th,  g_w1th); cudaGetSymbolAddress((void**)&w1tl, g_w1tl);
    cudaGetSymbolAddress((void**)&w2th,  g_w2th); cudaGetSymbolAddress((void**)&w2tl, g_w2tl);
    cudaGetSymbolAddress((void**)&dwth,  g_dwth); cudaGetSymbolAddress((void**)&dwtl, g_dwtl);
    cudaGetSymbolAddress((void**)&d1th,  g_d1th); cudaGetSymbolAddress((void**)&d1tl, g_d1tl);
    cudaGetSymbolAddress((void**)&d2th,  g_d2th); cudaGetSymbolAddress((void**)&d2tl, g_d2tl);

    // transpose + convert weights once per call
    wcvt(conv_w1, w1th, w1tl, DD, HH, KPD, LL);
    wcvt(conv_w2, w2th, w2tl, HH, DD, KPH, LL);
    wcvt(dist_w,  dwth, dwtl, DD, HH, KPD, 1);
    wcvt(dec_w1,  d1th, d1tl, DD, DECH, KPD, 6);
    wcvt(dec_w2,  d2th, d2tl, DECH, MAXO, KPDEC, 6);

    const long ND  = (long)NN * DD;
    const long ND4 = ND / 4;
    const long ED4 = (long)EE * DD / 4;
    const long NZP = (long)NN * KPD;
    const long NYP = (long)NN * KPH;

    k_init_h4<<<(int)((ND4 + 255) / 256), 256>>>((const float4*)atom_emb, x_idx, (float4*)h);

    for (int l = 0; l < LL; l++) {
        k_init_z4<<<(int)((ND4 + 255) / 256), 256>>>((const float4*)h, eps + l, (float4*)z);
        k_edge4<<<(int)((ED4 + 255) / 256), 256>>>((const float4*)h,
                 (const float4*)(edge_emb + (size_t)l * 5 * DD), edge_attr, edge_index, z);
        // z -> bf16 hi/lo
        k_cvtpad<<<(int)((NZP + 255) / 256), 256>>>(z, zh, zl, NZP, DD, KPD);
        // y = z @ w1 + b1 ; fused stats
        k_zero<<<(2 * HH + 255) / 256, 256>>>(stats, 2 * HH);
        tgemm(zh, zl, KPD, w1th + (size_t)l * HH * KPD, w1tl + (size_t)l * HH * KPD, KPD,
              conv_b1 + (size_t)l * HH, y, HH, NN, HH, KPD, stats, 1);
        k_bn_final<<<(HH + 255) / 256, 256>>>(stats, 1.f / (float)NN, HH,
              conv_bn1_g + (size_t)l * HH, conv_bn1_b + (size_t)l * HH, scale, shift);
        // relu(bn(y)) -> bf16 hi/lo
        k_bnact_cvt<<<(int)((NYP + 255) / 256), 256>>>(y, scale, shift, yh, yl, NYP, HH, KPH, 0);
        // z = y @ w2 + b2 ; fused stats ; h += act(bn)
        k_zero<<<(2 * DD + 255) / 256, 256>>>(stats, 2 * DD);
        tgemm(yh, yl, KPH, w2th + (size_t)l * DD * KPH, w2tl + (size_t)l * DD * KPH, KPH,
              conv_b2 + (size_t)l * DD, z, DD, NN, DD, KPH, stats, 1);
        k_bn_final<<<(DD + 255) / 256, 256>>>(stats, 1.f / (float)NN, DD,
              bn_g + (size_t)l * DD, bn_b + (size_t)l * DD, scale, shift);
        k_bn_apply4<<<(int)((ND4 + 255) / 256), 256>>>((float4*)z, (float4*)h,
              (const float4*)scale, (const float4*)shift, ND4, DD / 4, (l < LL - 1) ? 1 : 2);
    }

    // pooling -> silu -> bf16
    int GD = GG * DD;
    const long GSP = (long)GG * KPD;
    k_zero_u<<<(GD + 255) / 256, 256>>>(hg, GD);
    k_segmax<<<(int)((ND + 255) / 256), 256>>>(h, batch, hg);
    k_silu_cvt<<<(int)((GSP + 255) / 256), 256>>>(hg, sh, sl, GSP, DD, KPD);

    // d = silu(h_graph) @ dist_w + dist_b
    tgemm(sh, sl, KPD, dwth, dwtl, KPD, dist_b, dbuf, HH, GG, HH, KPD, stats, 0);

    const long OFF_SG = (long)GG * DD;
    k_split<<<(int)(((long)GG * HH + 255) / 256), 256>>>(dbuf, out, OFF_SG);
    // mu (= out[0..G*D)) -> bf16 hi/lo
    k_cvtpad<<<(int)((GSP + 255) / 256), 256>>>(out, muh, mul, GSP, DD, KPD);

    const long OFF_O0   = 2L * GG * DD;
    const long OFF_GENE = OFF_O0 + (long)GG * 1024;
    const long OFF_CELL = OFF_GENE + (long)GG * 1973;
    const long OFF_O5   = OFF_CELL + (long)GG * 2749;
    const int  dims[6] = {1024, 1111, 862, 1783, 966, 978};
    const long base[6] = {OFF_O0, OFF_GENE, OFF_GENE + 1111, OFF_CELL, OFF_CELL + 1783, OFF_O5};
    const int  ldcs[6] = {1024, 1973, 1973, 2749, 2749, 978};

    const long GDP = (long)GG * KPDEC;
    for (int i = 0; i < 6; i++) {
        k_zero<<<(2 * DECH + 255) / 256, 256>>>(stats, 2 * DECH);
        tgemm(muh, mul, KPD, d1th + (size_t)i * DECH * KPD, d1tl + (size_t)i * DECH * KPD, KPD,
              dec_b1 + (size_t)i * DECH, dz, DECH, GG, DECH, KPD, stats, 1);
        k_bn_final<<<(DECH + 255) / 256, 256>>>(stats, 1.f / (float)GG, DECH,
              dec_bn_g + (size_t)i * DECH, dec_bn_b + (size_t)i * DECH, scale, shift);
        k_bnact_cvt<<<(int)((GDP + 255) / 256), 256>>>(dz, scale, shift, dzh, dzl, GDP, DECH, KPDEC, 1);
        tgemm(dzh, dzl, KPDEC, d2th + (size_t)i * MAXO * KPDEC, d2tl + (size_t)i * MAXO * KPDEC, KPDEC,
              dec_b2 + (size_t)i * MAXO, out + base[i], ldcs[i], GG, dims[i], KPDEC, stats, 0);
    }
}